// round 3
// baseline (speedup 1.0000x reference)
#include <cuda_runtime.h>
#include <math.h>

// ---------------- problem constants ----------------
#define BB 2
#define SS 2048
#define DD 768
#define HH 12
#define DEPTH 64
#define DFF 3072
#define NROWS (BB*SS)          // 4096
#define LN_EPS 1e-5f

// ---------------- scratch (device globals: no allocs allowed) ----------------
__device__ float g_qkv[NROWS * 3 * DD];   // 4096 x 2304
__device__ float g_ctx[NROWS * DD];       // 4096 x 768
__device__ float g_tmp[NROWS * DD];       // attn_out / ffn_out
__device__ float g_h  [NROWS * DD];       // LN1 output
__device__ float g_ff [NROWS * DFF];      // 4096 x 3072

// ======================================================================
// SGEMM: C[M,N] = A[M,K] @ B[K,N] (+bias) (+relu)
// 128x128x8 tile, 256 threads, 8x8 per thread. Requires M%128==0, N%128==0, K%8==0.
// ======================================================================
template<bool BIAS, bool RELU>
__global__ __launch_bounds__(256, 2)
void sgemm128(const float* __restrict__ A, const float* __restrict__ Bm,
              const float* __restrict__ bias, float* __restrict__ C,
              int M, int N, int K)
{
    __shared__ float As[8][128];
    __shared__ float Bs[8][128];

    const int t    = threadIdx.x;
    const int brow = blockIdx.y * 128;
    const int bcol = blockIdx.x * 128;
    const int ty   = t >> 4;       // 0..15
    const int tx   = t & 15;       // 0..15

    const int arow = t >> 1;           // 0..127
    const int acol = (t & 1) * 4;      // 0 or 4
    const int brl  = t >> 5;           // 0..7
    const int bcl  = (t & 31) * 4;     // 0..124

    const float* Ap = A  + (size_t)(brow + arow) * K + acol;
    const float* Bp = Bm + (size_t)brl * N + bcol + bcl;

    float acc[8][8];
    #pragma unroll
    for (int i = 0; i < 8; i++)
        #pragma unroll
        for (int j = 0; j < 8; j++)
            acc[i][j] = 0.f;

    for (int k0 = 0; k0 < K; k0 += 8) {
        float4 av = *(const float4*)(Ap + k0);
        float4 bv = *(const float4*)(Bp + (size_t)k0 * N);
        As[acol + 0][arow] = av.x;
        As[acol + 1][arow] = av.y;
        As[acol + 2][arow] = av.z;
        As[acol + 3][arow] = av.w;
        *(float4*)&Bs[brl][bcl] = bv;
        __syncthreads();

        #pragma unroll
        for (int k = 0; k < 8; k++) {
            float ra[8], rb[8];
            *(float4*)(ra)     = *(const float4*)&As[k][ty * 8];
            *(float4*)(ra + 4) = *(const float4*)&As[k][ty * 8 + 4];
            *(float4*)(rb)     = *(const float4*)&Bs[k][tx * 8];
            *(float4*)(rb + 4) = *(const float4*)&Bs[k][tx * 8 + 4];
            #pragma unroll
            for (int i = 0; i < 8; i++)
                #pragma unroll
                for (int j = 0; j < 8; j++)
                    acc[i][j] = fmaf(ra[i], rb[j], acc[i][j]);
        }
        __syncthreads();
    }

    // epilogue
    #pragma unroll
    for (int i = 0; i < 8; i++) {
        const int row = brow + ty * 8 + i;
        #pragma unroll
        for (int j = 0; j < 8; j += 4) {
            const int col = bcol + tx * 8 + j;
            float4 v;
            v.x = acc[i][j];   v.y = acc[i][j+1];
            v.z = acc[i][j+2]; v.w = acc[i][j+3];
            if (BIAS) {
                v.x += bias[col];   v.y += bias[col+1];
                v.z += bias[col+2]; v.w += bias[col+3];
            }
            if (RELU) {
                v.x = fmaxf(v.x, 0.f); v.y = fmaxf(v.y, 0.f);
                v.z = fmaxf(v.z, 0.f); v.w = fmaxf(v.w, 0.f);
            }
            *(float4*)&C[(size_t)row * N + col] = v;
        }
    }
}

// ======================================================================
// Causal flash attention, fp32, DEPTH=64. 64-query x 64-key tiles.
// grid = (S/64, B*H), block = 256. Dynamic smem = 67584 B.
// qkv layout: row (b*S+s) x 2304; q at col h*64, k at 768+h*64, v at 1536+h*64.
// Output ctx: (b*S+s) x 768, head-concat layout.
// ======================================================================
#define ATTN_SMEM ((64*64*2 + 64*68*2) * 4)

__global__ __launch_bounds__(256)
void attn_kernel(const float* __restrict__ qkv, float* __restrict__ ctx)
{
    extern __shared__ float sm[];
    float* Qs = sm;               // [d][q]  64x64 (depth-major)
    float* Ks = Qs + 64 * 64;     // [d][k]  64x64
    float* Vs = Ks + 64 * 64;     // [k][d]  pitch 68
    float* Ps = Vs + 64 * 68;     // [k][q]  pitch 68

    const int qt = (gridDim.x - 1) - blockIdx.x;   // heavy tiles first
    const int bh = blockIdx.y;
    const int b  = bh / HH;
    const int h  = bh % HH;

    const float* base = qkv + (size_t)b * SS * (3 * DD);

    const int t  = threadIdx.x;
    const int ty = t >> 4, tx = t & 15;
    const int r0 = ty * 4, c0 = tx * 4;

    const int lr = t & 63;         // row within 64-tile
    const int ld = (t >> 6) * 16;  // depth chunk start

    // load Q tile (pre-scaled by 1/sqrt(64))
    {
        const float* qp = base + (size_t)(qt * 64 + lr) * (3 * DD) + h * 64 + ld;
        #pragma unroll
        for (int i = 0; i < 16; i += 4) {
            float4 v4 = *(const float4*)(qp + i);
            Qs[(ld + i + 0) * 64 + lr] = v4.x * 0.125f;
            Qs[(ld + i + 1) * 64 + lr] = v4.y * 0.125f;
            Qs[(ld + i + 2) * 64 + lr] = v4.z * 0.125f;
            Qs[(ld + i + 3) * 64 + lr] = v4.w * 0.125f;
        }
    }

    float O[4][4];
    float m[4], l[4];
    #pragma unroll
    for (int i = 0; i < 4; i++) {
        m[i] = -1e30f; l[i] = 0.f;
        #pragma unroll
        for (int j = 0; j < 4; j++) O[i][j] = 0.f;
    }

    for (int kt = 0; kt <= qt; kt++) {
        __syncthreads();   // protect Ks/Vs (+ first-iter Qs) from prior reads
        {
            const float* kp = base + (size_t)(kt * 64 + lr) * (3 * DD) + DD + h * 64 + ld;
            const float* vp = kp + DD;
            #pragma unroll
            for (int i = 0; i < 16; i += 4) {
                float4 kv = *(const float4*)(kp + i);
                Ks[(ld + i + 0) * 64 + lr] = kv.x;
                Ks[(ld + i + 1) * 64 + lr] = kv.y;
                Ks[(ld + i + 2) * 64 + lr] = kv.z;
                Ks[(ld + i + 3) * 64 + lr] = kv.w;
                float4 vv = *(const float4*)(vp + i);
                *(float4*)&Vs[lr * 68 + ld + i] = vv;
            }
        }
        __syncthreads();

        // scores: s = (Q/8) @ K^T  (64x64x64)
        float s[4][4];
        #pragma unroll
        for (int i = 0; i < 4; i++)
            #pragma unroll
            for (int j = 0; j < 4; j++) s[i][j] = 0.f;

        #pragma unroll 4
        for (int d = 0; d < 64; d++) {
            float4 a  = *(const float4*)&Qs[d * 64 + r0];
            float4 bq = *(const float4*)&Ks[d * 64 + c0];
            float ra[4] = {a.x, a.y, a.z, a.w};
            float rb[4] = {bq.x, bq.y, bq.z, bq.w};
            #pragma unroll
            for (int i = 0; i < 4; i++)
                #pragma unroll
                for (int j = 0; j < 4; j++)
                    s[i][j] = fmaf(ra[i], rb[j], s[i][j]);
        }

        // causal mask on diagonal tile
        if (kt == qt) {
            #pragma unroll
            for (int i = 0; i < 4; i++)
                #pragma unroll
                for (int j = 0; j < 4; j++)
                    if (c0 + j > r0 + i) s[i][j] = -1e30f;
        }

        // online softmax
        #pragma unroll
        for (int i = 0; i < 4; i++) {
            float rmax = fmaxf(fmaxf(s[i][0], s[i][1]), fmaxf(s[i][2], s[i][3]));
            #pragma unroll
            for (int o = 8; o >= 1; o >>= 1)
                rmax = fmaxf(rmax, __shfl_xor_sync(0xffffffffu, rmax, o));
            float mn = fmaxf(m[i], rmax);
            float scale = __expf(m[i] - mn);
            float rsum = 0.f;
            #pragma unroll
            for (int j = 0; j < 4; j++) {
                float p = __expf(s[i][j] - mn);
                s[i][j] = p;
                rsum += p;
            }
            #pragma unroll
            for (int o = 8; o >= 1; o >>= 1)
                rsum += __shfl_xor_sync(0xffffffffu, rsum, o);
            l[i] = l[i] * scale + rsum;
            m[i] = mn;
            #pragma unroll
            for (int j = 0; j < 4; j++) O[i][j] *= scale;
        }

        // write P transposed: Ps[key][query]
        #pragma unroll
        for (int j = 0; j < 4; j++)
            #pragma unroll
            for (int i = 0; i < 4; i++)
                Ps[(c0 + j) * 68 + (r0 + i)] = s[i][j];
        __syncthreads();

        // O += P @ V   (64x64x64)
        #pragma unroll 4
        for (int k = 0; k < 64; k++) {
            float4 pv = *(const float4*)&Ps[k * 68 + r0];
            float4 vv = *(const float4*)&Vs[k * 68 + c0];
            float rp[4] = {pv.x, pv.y, pv.z, pv.w};
            float rv[4] = {vv.x, vv.y, vv.z, vv.w};
            #pragma unroll
            for (int i = 0; i < 4; i++)
                #pragma unroll
                for (int j = 0; j < 4; j++)
                    O[i][j] = fmaf(rp[i], rv[j], O[i][j]);
        }
    }

    // write ctx (head-concat): ctx[(b*S+q)*768 + h*64 + d]
    #pragma unroll
    for (int i = 0; i < 4; i++) {
        const float inv = 1.f / l[i];
        const size_t row = (size_t)(b * SS + qt * 64 + r0 + i) * DD + h * 64 + c0;
        float4 v;
        v.x = O[i][0] * inv; v.y = O[i][1] * inv;
        v.z = O[i][2] * inv; v.w = O[i][3] * inv;
        *(float4*)&ctx[row] = v;
    }
}

// ======================================================================
// Fused residual + LayerNorm: out = gain * norm(a+b) + beta, row length 768.
// grid = NROWS, block = 256 (3 elements/thread).
// ======================================================================
__global__ __launch_bounds__(256)
void ln_residual(const float* __restrict__ a, const float* __restrict__ b,
                 const float* __restrict__ gain, const float* __restrict__ beta,
                 float* __restrict__ out)
{
    const int row = blockIdx.x;
    const float* pa = a + (size_t)row * DD;
    const float* pb = b + (size_t)row * DD;

    float v[3];
    float s = 0.f, s2 = 0.f;
    #pragma unroll
    for (int i = 0; i < 3; i++) {
        const int c = threadIdx.x + i * 256;
        float x = pa[c] + pb[c];
        v[i] = x;
        s  += x;
        s2 = fmaf(x, x, s2);
    }

    __shared__ float sm1[8], sm2[8];
    #pragma unroll
    for (int o = 16; o >= 1; o >>= 1) {
        s  += __shfl_xor_sync(0xffffffffu, s,  o);
        s2 += __shfl_xor_sync(0xffffffffu, s2, o);
    }
    const int w = threadIdx.x >> 5, lane = threadIdx.x & 31;
    if (lane == 0) { sm1[w] = s; sm2[w] = s2; }
    __syncthreads();
    if (w == 0) {
        s  = (lane < 8) ? sm1[lane] : 0.f;
        s2 = (lane < 8) ? sm2[lane] : 0.f;
        #pragma unroll
        for (int o = 4; o >= 1; o >>= 1) {
            s  += __shfl_xor_sync(0xffffffffu, s,  o);
            s2 += __shfl_xor_sync(0xffffffffu, s2, o);
        }
        if (lane == 0) { sm1[0] = s; sm2[0] = s2; }
    }
    __syncthreads();

    const float mean = sm1[0] * (1.f / DD);
    const float var  = sm2[0] * (1.f / DD) - mean * mean;
    const float inv  = rsqrtf(var + LN_EPS);

    #pragma unroll
    for (int i = 0; i < 3; i++) {
        const int c = threadIdx.x + i * 256;
        out[(size_t)row * DD + c] = gain[c] * (v[i] - mean) * inv + beta[c];
    }
}

// ======================================================================
// launch
// ======================================================================
extern "C" void kernel_launch(void* const* d_in, const int* in_sizes, int n_in,
                              void* d_out, int out_size)
{
    const float* x    = (const float*)d_in[0];
    const float* Wqkv = (const float*)d_in[1];
    const float* Wout = (const float*)d_in[2];
    const float* bout = (const float*)d_in[3];
    const float* W1   = (const float*)d_in[4];
    const float* b1   = (const float*)d_in[5];
    const float* W2   = (const float*)d_in[6];
    const float* b2   = (const float*)d_in[7];
    const float* g1   = (const float*)d_in[8];
    const float* be1  = (const float*)d_in[9];
    const float* g2   = (const float*)d_in[10];
    const float* be2  = (const float*)d_in[11];
    float* out = (float*)d_out;

    float *qkv, *ctx, *tmp, *h, *ff;
    cudaGetSymbolAddress((void**)&qkv, g_qkv);
    cudaGetSymbolAddress((void**)&ctx, g_ctx);
    cudaGetSymbolAddress((void**)&tmp, g_tmp);
    cudaGetSymbolAddress((void**)&h,   g_h);
    cudaGetSymbolAddress((void**)&ff,  g_ff);

    cudaFuncSetAttribute(attn_kernel,
                         cudaFuncAttributeMaxDynamicSharedMemorySize, ATTN_SMEM);

    dim3 blk(256);

    // 1) QKV projection: (4096x768) @ (768x2304)
    sgemm128<false, false><<<dim3((3 * DD) / 128, NROWS / 128), blk>>>(
        x, Wqkv, nullptr, qkv, NROWS, 3 * DD, DD);

    // 2) causal attention -> ctx
    attn_kernel<<<dim3(SS / 64, BB * HH), blk, ATTN_SMEM>>>(qkv, ctx);

    // 3) output projection + bias
    sgemm128<true, false><<<dim3(DD / 128, NROWS / 128), blk>>>(
        ctx, Wout, bout, tmp, NROWS, DD, DD);

    // 4) LN1(x + attn_out) -> h
    ln_residual<<<NROWS, 256>>>(x, tmp, g1, be1, h);

    // 5) FFN up + bias + relu
    sgemm128<true, true><<<dim3(DFF / 128, NROWS / 128), blk>>>(
        h, W1, b1, ff, NROWS, DFF, DD);

    // 6) FFN down + bias
    sgemm128<true, false><<<dim3(DD / 128, NROWS / 128), blk>>>(
        ff, W2, b2, tmp, NROWS, DD, DFF);

    // 7) LN2(h + ff) -> out
    ln_residual<<<NROWS, 256>>>(h, tmp, g2, be2, out);
}

// round 5
// speedup vs baseline: 1.4576x; 1.4576x over previous
#include <cuda_runtime.h>
#include <cuda_bf16.h>
#include <stdint.h>
#include <math.h>

// ---------------- problem constants ----------------
#define BB 2
#define SS 2048
#define DD 768
#define HH 12
#define DEPTH 64
#define DFF 3072
#define NROWS (BB*SS)          // 4096
#define LN_EPS 1e-5f

// ---------------- scratch (device globals: no allocs allowed) ----------------
__device__ float g_qkv[NROWS * 3 * DD];   // 4096 x 2304
__device__ float g_ctx[NROWS * DD];       // 4096 x 768
__device__ float g_tmp[NROWS * DD];       // attn_out / ffn_out
__device__ float g_h  [NROWS * DD];       // LN1 output
__device__ float g_ff [NROWS * DFF];      // 4096 x 3072

// ======================================================================
// Tensor-core GEMM (bf16 split-3): C = A @ B (+bias)(+relu), fp32 in/out.
// Each fp32 operand is split into hi+lo bf16; C = Ah*Bh + Ah*Bl + Al*Bh.
// Tile 128x128x32, 256 threads (8 warps, 2x4), warp tile 64x32 via
// mma.sync.m16n8k16. Requires M%128==0, N%128==0, K%32==0.
// ======================================================================
#define PITCH 136   // uint32 pitch; pad 8 -> conflict-free fragment loads

__device__ __forceinline__ void split2(float a, float b, uint32_t& hi, uint32_t& lo)
{
    // pack (a,b) with a in low 16 bits (lower k index)
    __nv_bfloat16 ah = __float2bfloat16(a);
    __nv_bfloat16 bh = __float2bfloat16(b);
    __nv_bfloat16 al = __float2bfloat16(a - __bfloat162float(ah));
    __nv_bfloat16 bl = __float2bfloat16(b - __bfloat162float(bh));
    hi = (uint32_t)__bfloat16_as_ushort(ah) | ((uint32_t)__bfloat16_as_ushort(bh) << 16);
    lo = (uint32_t)__bfloat16_as_ushort(al) | ((uint32_t)__bfloat16_as_ushort(bl) << 16);
}

__device__ __forceinline__ void mma16816(float* c, const uint32_t* a, const uint32_t* b)
{
    asm volatile(
        "mma.sync.aligned.m16n8k16.row.col.f32.bf16.bf16.f32 "
        "{%0,%1,%2,%3}, {%4,%5,%6,%7}, {%8,%9}, {%0,%1,%2,%3};"
        : "+f"(c[0]), "+f"(c[1]), "+f"(c[2]), "+f"(c[3])
        : "r"(a[0]), "r"(a[1]), "r"(a[2]), "r"(a[3]),
          "r"(b[0]), "r"(b[1]));
}

template<bool BIAS, bool RELU>
__global__ __launch_bounds__(256)
void gemm_bf16x3(const float* __restrict__ A, const float* __restrict__ Bm,
                 const float* __restrict__ bias, float* __restrict__ C,
                 int M, int N, int K)
{
    // packed bf16x2 tiles: index [k-pair][m or n]
    __shared__ uint32_t sAh[16][PITCH], sAl[16][PITCH];
    __shared__ uint32_t sBh[16][PITCH], sBl[16][PITCH];

    const int t    = threadIdx.x;
    const int brow = blockIdx.y * 128;
    const int bcol = blockIdx.x * 128;
    const int warp = t >> 5, lane = t & 31;
    const int wr   = warp >> 2, wc = warp & 3;   // warp grid 2x4
    const int g    = lane >> 2, cq = lane & 3;   // fragment coords

    float4 ra[4];      // A prefetch: 128x32 / 256 thr = 4 float4
    float4 rb[2][2];   // B prefetch: 2 items x 2 rows

    float c[4][4][4];
    #pragma unroll
    for (int mf = 0; mf < 4; mf++)
        #pragma unroll
        for (int nf = 0; nf < 4; nf++)
            #pragma unroll
            for (int r = 0; r < 4; r++) c[mf][nf][r] = 0.f;

    const int S = K >> 5;   // K/32 stages

    // ---- stage-0 global loads ----
    #pragma unroll
    for (int i = 0; i < 4; i++) {
        int idx = i * 256 + t;
        int m = idx >> 3, kq = idx & 7;
        ra[i] = *(const float4*)(A + (size_t)(brow + m) * K + kq * 4);
    }
    #pragma unroll
    for (int j = 0; j < 2; j++) {
        int idx = j * 256 + t;
        int kp = idx >> 5, nq = idx & 31;
        const float* p = Bm + (size_t)(kp * 2) * N + bcol + nq * 4;
        rb[j][0] = *(const float4*)p;
        rb[j][1] = *(const float4*)(p + N);
    }

    for (int s = 0; s < S; s++) {
        // ---- convert + store to smem ----
        #pragma unroll
        for (int i = 0; i < 4; i++) {
            int idx = i * 256 + t;
            int m = idx >> 3, kq = idx & 7;
            uint32_t h0, l0, h1, l1;
            split2(ra[i].x, ra[i].y, h0, l0);
            split2(ra[i].z, ra[i].w, h1, l1);
            sAh[kq * 2][m]     = h0;  sAl[kq * 2][m]     = l0;
            sAh[kq * 2 + 1][m] = h1;  sAl[kq * 2 + 1][m] = l1;
        }
        #pragma unroll
        for (int j = 0; j < 2; j++) {
            int idx = j * 256 + t;
            int kp = idx >> 5, nq = idx & 31;
            float r0[4] = {rb[j][0].x, rb[j][0].y, rb[j][0].z, rb[j][0].w};
            float r1[4] = {rb[j][1].x, rb[j][1].y, rb[j][1].z, rb[j][1].w};
            #pragma unroll
            for (int e = 0; e < 4; e++) {
                uint32_t h, l;
                split2(r0[e], r1[e], h, l);   // low = row 2kp (lower k)
                sBh[kp][nq * 4 + e] = h;
                sBl[kp][nq * 4 + e] = l;
            }
        }
        __syncthreads();

        // ---- prefetch next stage (overlaps with MMA below) ----
        if (s + 1 < S) {
            const int kbase = (s + 1) * 32;
            #pragma unroll
            for (int i = 0; i < 4; i++) {
                int idx = i * 256 + t;
                int m = idx >> 3, kq = idx & 7;
                ra[i] = *(const float4*)(A + (size_t)(brow + m) * K + kbase + kq * 4);
            }
            #pragma unroll
            for (int j = 0; j < 2; j++) {
                int idx = j * 256 + t;
                int kp = idx >> 5, nq = idx & 31;
                const float* p = Bm + (size_t)(kbase + kp * 2) * N + bcol + nq * 4;
                rb[j][0] = *(const float4*)p;
                rb[j][1] = *(const float4*)(p + N);
            }
        }

        // ---- compute: 2 x k16 steps ----
        #pragma unroll
        for (int ks = 0; ks < 2; ks++) {
            uint32_t bh[4][2], bl[4][2];
            #pragma unroll
            for (int nf = 0; nf < 4; nf++) {
                const int col = wc * 32 + nf * 8 + g;
                bh[nf][0] = sBh[ks * 8 + cq][col];
                bh[nf][1] = sBh[ks * 8 + cq + 4][col];
                bl[nf][0] = sBl[ks * 8 + cq][col];
                bl[nf][1] = sBl[ks * 8 + cq + 4][col];
            }
            #pragma unroll
            for (int mf = 0; mf < 4; mf++) {
                const int row = wr * 64 + mf * 16;
                uint32_t ah[4], al[4];
                ah[0] = sAh[ks * 8 + cq][row + g];
                ah[1] = sAh[ks * 8 + cq][row + g + 8];
                ah[2] = sAh[ks * 8 + cq + 4][row + g];
                ah[3] = sAh[ks * 8 + cq + 4][row + g + 8];
                al[0] = sAl[ks * 8 + cq][row + g];
                al[1] = sAl[ks * 8 + cq][row + g + 8];
                al[2] = sAl[ks * 8 + cq + 4][row + g];
                al[3] = sAl[ks * 8 + cq + 4][row + g + 8];
                // interleave passes across nf to break RAW chains on C frags
                #pragma unroll
                for (int nf = 0; nf < 4; nf++) mma16816(c[mf][nf], ah, bh[nf]);
                #pragma unroll
                for (int nf = 0; nf < 4; nf++) mma16816(c[mf][nf], ah, bl[nf]);
                #pragma unroll
                for (int nf = 0; nf < 4; nf++) mma16816(c[mf][nf], al, bh[nf]);
            }
        }
        __syncthreads();
    }

    // ---- epilogue ----
    #pragma unroll
    for (int mf = 0; mf < 4; mf++) {
        const int row = brow + wr * 64 + mf * 16 + g;
        #pragma unroll
        for (int nf = 0; nf < 4; nf++) {
            const int col = bcol + wc * 32 + nf * 8 + cq * 2;
            float2 v0 = make_float2(c[mf][nf][0], c[mf][nf][1]);
            float2 v1 = make_float2(c[mf][nf][2], c[mf][nf][3]);
            if (BIAS) {
                float2 bv = *(const float2*)(bias + col);
                v0.x += bv.x; v0.y += bv.y;
                v1.x += bv.x; v1.y += bv.y;
            }
            if (RELU) {
                v0.x = fmaxf(v0.x, 0.f); v0.y = fmaxf(v0.y, 0.f);
                v1.x = fmaxf(v1.x, 0.f); v1.y = fmaxf(v1.y, 0.f);
            }
            *(float2*)(C + (size_t)row * N + col)       = v0;
            *(float2*)(C + (size_t)(row + 8) * N + col) = v1;
        }
    }
}

// ======================================================================
// Causal flash attention, fp32, DEPTH=64. 64-query x 64-key tiles.
// grid = (S/64, B*H), block = 256. Dynamic smem = 67584 B.
// ======================================================================
#define ATTN_SMEM ((64*64*2 + 64*68*2) * 4)

__global__ __launch_bounds__(256)
void attn_kernel(const float* __restrict__ qkv, float* __restrict__ ctx)
{
    extern __shared__ float sm[];
    float* Qs = sm;               // [d][q]  64x64 (depth-major)
    float* Ks = Qs + 64 * 64;     // [d][k]  64x64
    float* Vs = Ks + 64 * 64;     // [k][d]  pitch 68
    float* Ps = Vs + 64 * 68;     // [k][q]  pitch 68

    const int qt = (gridDim.x - 1) - blockIdx.x;   // heavy tiles first
    const int bh = blockIdx.y;
    const int b  = bh / HH;
    const int h  = bh % HH;

    const float* base = qkv + (size_t)b * SS * (3 * DD);

    const int t  = threadIdx.x;
    const int ty = t >> 4, tx = t & 15;
    const int r0 = ty * 4, c0 = tx * 4;

    const int lr = t & 63;
    const int ld = (t >> 6) * 16;

    {
        const float* qp = base + (size_t)(qt * 64 + lr) * (3 * DD) + h * 64 + ld;
        #pragma unroll
        for (int i = 0; i < 16; i += 4) {
            float4 v4 = *(const float4*)(qp + i);
            Qs[(ld + i + 0) * 64 + lr] = v4.x * 0.125f;
            Qs[(ld + i + 1) * 64 + lr] = v4.y * 0.125f;
            Qs[(ld + i + 2) * 64 + lr] = v4.z * 0.125f;
            Qs[(ld + i + 3) * 64 + lr] = v4.w * 0.125f;
        }
    }

    float O[4][4];
    float m[4], l[4];
    #pragma unroll
    for (int i = 0; i < 4; i++) {
        m[i] = -1e30f; l[i] = 0.f;
        #pragma unroll
        for (int j = 0; j < 4; j++) O[i][j] = 0.f;
    }

    for (int kt = 0; kt <= qt; kt++) {
        __syncthreads();
        {
            const float* kp = base + (size_t)(kt * 64 + lr) * (3 * DD) + DD + h * 64 + ld;
            const float* vp = kp + DD;
            #pragma unroll
            for (int i = 0; i < 16; i += 4) {
                float4 kv = *(const float4*)(kp + i);
                Ks[(ld + i + 0) * 64 + lr] = kv.x;
                Ks[(ld + i + 1) * 64 + lr] = kv.y;
                Ks[(ld + i + 2) * 64 + lr] = kv.z;
                Ks[(ld + i + 3) * 64 + lr] = kv.w;
                float4 vv = *(const float4*)(vp + i);
                *(float4*)&Vs[lr * 68 + ld + i] = vv;
            }
        }
        __syncthreads();

        float s[4][4];
        #pragma unroll
        for (int i = 0; i < 4; i++)
            #pragma unroll
            for (int j = 0; j < 4; j++) s[i][j] = 0.f;

        #pragma unroll 4
        for (int d = 0; d < 64; d++) {
            float4 a  = *(const float4*)&Qs[d * 64 + r0];
            float4 bq = *(const float4*)&Ks[d * 64 + c0];
            float raf[4] = {a.x, a.y, a.z, a.w};
            float rbf[4] = {bq.x, bq.y, bq.z, bq.w};
            #pragma unroll
            for (int i = 0; i < 4; i++)
                #pragma unroll
                for (int j = 0; j < 4; j++)
                    s[i][j] = fmaf(raf[i], rbf[j], s[i][j]);
        }

        if (kt == qt) {
            #pragma unroll
            for (int i = 0; i < 4; i++)
                #pragma unroll
                for (int j = 0; j < 4; j++)
                    if (c0 + j > r0 + i) s[i][j] = -1e30f;
        }

        #pragma unroll
        for (int i = 0; i < 4; i++) {
            float rmax = fmaxf(fmaxf(s[i][0], s[i][1]), fmaxf(s[i][2], s[i][3]));
            #pragma unroll
            for (int o = 8; o >= 1; o >>= 1)
                rmax = fmaxf(rmax, __shfl_xor_sync(0xffffffffu, rmax, o));
            float mn = fmaxf(m[i], rmax);
            float scale = __expf(m[i] - mn);
            float rsum = 0.f;
            #pragma unroll
            for (int j = 0; j < 4; j++) {
                float p = __expf(s[i][j] - mn);
                s[i][j] = p;
                rsum += p;
            }
            #pragma unroll
            for (int o = 8; o >= 1; o >>= 1)
                rsum += __shfl_xor_sync(0xffffffffu, rsum, o);
            l[i] = l[i] * scale + rsum;
            m[i] = mn;
            #pragma unroll
            for (int j = 0; j < 4; j++) O[i][j] *= scale;
        }

        #pragma unroll
        for (int j = 0; j < 4; j++)
            #pragma unroll
            for (int i = 0; i < 4; i++)
                Ps[(c0 + j) * 68 + (r0 + i)] = s[i][j];
        __syncthreads();

        #pragma unroll 4
        for (int k = 0; k < 64; k++) {
            float4 pv = *(const float4*)&Ps[k * 68 + r0];
            float4 vv = *(const float4*)&Vs[k * 68 + c0];
            float rp[4] = {pv.x, pv.y, pv.z, pv.w};
            float rv[4] = {vv.x, vv.y, vv.z, vv.w};
            #pragma unroll
            for (int i = 0; i < 4; i++)
                #pragma unroll
                for (int j = 0; j < 4; j++)
                    O[i][j] = fmaf(rp[i], rv[j], O[i][j]);
        }
    }

    #pragma unroll
    for (int i = 0; i < 4; i++) {
        const float inv = 1.f / l[i];
        const size_t row = (size_t)(b * SS + qt * 64 + r0 + i) * DD + h * 64 + c0;
        float4 v;
        v.x = O[i][0] * inv; v.y = O[i][1] * inv;
        v.z = O[i][2] * inv; v.w = O[i][3] * inv;
        *(float4*)&ctx[row] = v;
    }
}

// ======================================================================
// Fused residual + LayerNorm: out = gain * norm(a+b) + beta, row length 768.
// ======================================================================
__global__ __launch_bounds__(256)
void ln_residual(const float* __restrict__ a, const float* __restrict__ b,
                 const float* __restrict__ gain, const float* __restrict__ beta,
                 float* __restrict__ out)
{
    const int row = blockIdx.x;
    const float* pa = a + (size_t)row * DD;
    const float* pb = b + (size_t)row * DD;

    float v[3];
    float s = 0.f, s2 = 0.f;
    #pragma unroll
    for (int i = 0; i < 3; i++) {
        const int c = threadIdx.x + i * 256;
        float x = pa[c] + pb[c];
        v[i] = x;
        s  += x;
        s2 = fmaf(x, x, s2);
    }

    __shared__ float sm1[8], sm2[8];
    #pragma unroll
    for (int o = 16; o >= 1; o >>= 1) {
        s  += __shfl_xor_sync(0xffffffffu, s,  o);
        s2 += __shfl_xor_sync(0xffffffffu, s2, o);
    }
    const int w = threadIdx.x >> 5, lane = threadIdx.x & 31;
    if (lane == 0) { sm1[w] = s; sm2[w] = s2; }
    __syncthreads();
    if (w == 0) {
        s  = (lane < 8) ? sm1[lane] : 0.f;
        s2 = (lane < 8) ? sm2[lane] : 0.f;
        #pragma unroll
        for (int o = 4; o >= 1; o >>= 1) {
            s  += __shfl_xor_sync(0xffffffffu, s,  o);
            s2 += __shfl_xor_sync(0xffffffffu, s2, o);
        }
        if (lane == 0) { sm1[0] = s; sm2[0] = s2; }
    }
    __syncthreads();

    const float mean = sm1[0] * (1.f / DD);
    const float var  = sm2[0] * (1.f / DD) - mean * mean;
    const float inv  = rsqrtf(var + LN_EPS);

    #pragma unroll
    for (int i = 0; i < 3; i++) {
        const int c = threadIdx.x + i * 256;
        out[(size_t)row * DD + c] = gain[c] * (v[i] - mean) * inv + beta[c];
    }
}

// ======================================================================
// launch
// ======================================================================
extern "C" void kernel_launch(void* const* d_in, const int* in_sizes, int n_in,
                              void* d_out, int out_size)
{
    const float* x    = (const float*)d_in[0];
    const float* Wqkv = (const float*)d_in[1];
    const float* Wout = (const float*)d_in[2];
    const float* bout = (const float*)d_in[3];
    const float* W1   = (const float*)d_in[4];
    const float* b1   = (const float*)d_in[5];
    const float* W2   = (const float*)d_in[6];
    const float* b2   = (const float*)d_in[7];
    const float* g1   = (const float*)d_in[8];
    const float* be1  = (const float*)d_in[9];
    const float* g2   = (const float*)d_in[10];
    const float* be2  = (const float*)d_in[11];
    float* out = (float*)d_out;

    float *qkv, *ctx, *tmp, *h, *ff;
    cudaGetSymbolAddress((void**)&qkv, g_qkv);
    cudaGetSymbolAddress((void**)&ctx, g_ctx);
    cudaGetSymbolAddress((void**)&tmp, g_tmp);
    cudaGetSymbolAddress((void**)&h,   g_h);
    cudaGetSymbolAddress((void**)&ff,  g_ff);

    cudaFuncSetAttribute(attn_kernel,
                         cudaFuncAttributeMaxDynamicSharedMemorySize, ATTN_SMEM);

    dim3 blk(256);

    // 1) QKV projection: (4096x768) @ (768x2304)
    gemm_bf16x3<false, false><<<dim3((3 * DD) / 128, NROWS / 128), blk>>>(
        x, Wqkv, nullptr, qkv, NROWS, 3 * DD, DD);

    // 2) causal attention -> ctx
    attn_kernel<<<dim3(SS / 64, BB * HH), blk, ATTN_SMEM>>>(qkv, ctx);

    // 3) output projection + bias
    gemm_bf16x3<true, false><<<dim3(DD / 128, NROWS / 128), blk>>>(
        ctx, Wout, bout, tmp, NROWS, DD, DD);

    // 4) LN1(x + attn_out) -> h
    ln_residual<<<NROWS, 256>>>(x, tmp, g1, be1, h);

    // 5) FFN up + bias + relu
    gemm_bf16x3<true, true><<<dim3(DFF / 128, NROWS / 128), blk>>>(
        h, W1, b1, ff, NROWS, DFF, DD);

    // 6) FFN down + bias
    gemm_bf16x3<true, false><<<dim3(DD / 128, NROWS / 128), blk>>>(
        ff, W2, b2, tmp, NROWS, DD, DFF);

    // 7) LN2(h + ff) -> out
    ln_residual<<<NROWS, 256>>>(h, tmp, g2, be2, out);
}

// round 6
// speedup vs baseline: 1.5701x; 1.0772x over previous
#include <cuda_runtime.h>
#include <cuda_bf16.h>
#include <stdint.h>
#include <math.h>

// ---------------- problem constants ----------------
#define BB 2
#define SS 2048
#define DD 768
#define HH 12
#define DEPTH 64
#define DFF 3072
#define NROWS (BB*SS)          // 4096
#define LN_EPS 1e-5f

// ---------------- fp32 scratch ----------------
__device__ float g_qkv[NROWS * 3 * DD];   // 4096 x 2304
__device__ float g_tmp[NROWS * DD];       // attn_out / ffn_out
__device__ float g_h  [NROWS * DD];       // LN1 output (fp32, for residual)

// ---------------- bf16 hi/lo scratch (uint32 = packed bf16x2) ----------------
// activations, flat [M,K] bf16 (uint32 = k-pair)
__device__ uint32_t g_xh  [NROWS * DD  / 2], g_xl  [NROWS * DD  / 2];
__device__ uint32_t g_ctxh[NROWS * DD  / 2], g_ctxl[NROWS * DD  / 2];
__device__ uint32_t g_hh  [NROWS * DD  / 2], g_hl  [NROWS * DD  / 2];
__device__ uint32_t g_ffh [NROWS * DFF / 2], g_ffl [NROWS * DFF / 2];
// weights, k-pair packed: [K/2][N] uint32, elem (kp,n) = (W[2kp][n], W[2kp+1][n])
__device__ uint32_t g_wqkvh[(DD/2)  * 3*DD], g_wqkvl[(DD/2)  * 3*DD];
__device__ uint32_t g_wouth[(DD/2)  * DD  ], g_woutl[(DD/2)  * DD  ];
__device__ uint32_t g_w1h  [(DD/2)  * DFF ], g_w1l  [(DD/2)  * DFF ];
__device__ uint32_t g_w2h  [(DFF/2) * DD  ], g_w2l  [(DFF/2) * DD  ];

// ======================================================================
// split helpers
// ======================================================================
__device__ __forceinline__ void split2(float a, float b, uint32_t& hi, uint32_t& lo)
{
    // pack (a,b) with a in low 16 bits (lower k index)
    __nv_bfloat16 ah = __float2bfloat16(a);
    __nv_bfloat16 bh = __float2bfloat16(b);
    __nv_bfloat16 al = __float2bfloat16(a - __bfloat162float(ah));
    __nv_bfloat16 bl = __float2bfloat16(b - __bfloat162float(bh));
    hi = (uint32_t)__bfloat16_as_ushort(ah) | ((uint32_t)__bfloat16_as_ushort(bh) << 16);
    lo = (uint32_t)__bfloat16_as_ushort(al) | ((uint32_t)__bfloat16_as_ushort(bl) << 16);
}

// activation split: fp32 [M,K] -> hi/lo packed k-pairs (flat)
__global__ __launch_bounds__(256)
void split_act(const float* __restrict__ in, uint32_t* __restrict__ hi,
               uint32_t* __restrict__ lo, int n_pairs)
{
    int i = blockIdx.x * 256 + threadIdx.x;
    if (i < n_pairs) {
        float2 v = ((const float2*)in)[i];
        uint32_t h, l;
        split2(v.x, v.y, h, l);
        hi[i] = h; lo[i] = l;
    }
}

// weight split: fp32 [K,N] -> kpair-packed [K/2][N]
__global__ __launch_bounds__(256)
void split_wgt(const float* __restrict__ W, uint32_t* __restrict__ hi,
               uint32_t* __restrict__ lo, int K2, int N)
{
    int idx = blockIdx.x * 256 + threadIdx.x;
    if (idx < K2 * N) {
        int kp = idx / N, n = idx - kp * N;
        float a = W[(size_t)(2 * kp) * N + n];
        float b = W[(size_t)(2 * kp + 1) * N + n];
        uint32_t h, l;
        split2(a, b, h, l);
        hi[idx] = h; lo[idx] = l;
    }
}

// ======================================================================
// Tensor-core GEMM (pre-split bf16 hi/lo): C = A @ B (+bias)(+relu).
// A: flat bf16 [M,K] hi/lo (uint32 k-pairs). B: kpair-packed [K/2][N] hi/lo.
// C = Ah*Bh + Ah*Bl + Al*Bh (fp32 accum). Tile 128x128x32, 256 thr, 8 warps.
// OUTBF16: write C split to bf16 hi/lo instead of fp32.
// ======================================================================
#define PITCH 136   // uint32 pitch; conflict-free fragment loads

__device__ __forceinline__ void mma16816(float* c, const uint32_t* a, const uint32_t* b)
{
    asm volatile(
        "mma.sync.aligned.m16n8k16.row.col.f32.bf16.bf16.f32 "
        "{%0,%1,%2,%3}, {%4,%5,%6,%7}, {%8,%9}, {%0,%1,%2,%3};"
        : "+f"(c[0]), "+f"(c[1]), "+f"(c[2]), "+f"(c[3])
        : "r"(a[0]), "r"(a[1]), "r"(a[2]), "r"(a[3]),
          "r"(b[0]), "r"(b[1]));
}

template<bool BIAS, bool RELU, bool OUTBF16>
__global__ __launch_bounds__(256)
void gemm_pre(const uint32_t* __restrict__ Ahi, const uint32_t* __restrict__ Alo,
              const uint32_t* __restrict__ Bhi, const uint32_t* __restrict__ Blo,
              const float* __restrict__ bias, float* __restrict__ C,
              uint32_t* __restrict__ Chi, uint32_t* __restrict__ Clo,
              int M, int N, int K)
{
    __shared__ uint32_t sAh[16][PITCH], sAl[16][PITCH];
    __shared__ uint32_t sBh[16][PITCH], sBl[16][PITCH];

    const int t    = threadIdx.x;
    const int brow = blockIdx.y * 128;
    const int bcol = blockIdx.x * 128;
    const int warp = t >> 5, lane = t & 31;
    const int wr   = warp >> 2, wc = warp & 3;   // warp grid 2x4
    const int g    = lane >> 2, cq = lane & 3;   // fragment coords
    const int K2   = K >> 1;                     // uint32 per A row

    uint4 rah[2], ral[2];   // A prefetch: 128x16 u32 / 256 thr = 2 uint4
    uint4 rbh[2], rbl[2];   // B prefetch: 16x128 u32 / 256 thr = 2 uint4

    float c[4][4][4];
    #pragma unroll
    for (int mf = 0; mf < 4; mf++)
        #pragma unroll
        for (int nf = 0; nf < 4; nf++)
            #pragma unroll
            for (int r = 0; r < 4; r++) c[mf][nf][r] = 0.f;

    const int S = K >> 5;   // K/32 stages (16 u32 kpairs per stage)

    // ---- stage-0 global loads ----
    #pragma unroll
    for (int i = 0; i < 2; i++) {
        int idx = i * 256 + t;
        int m = idx >> 2, kq = (idx & 3) * 4;
        size_t off = (size_t)(brow + m) * K2 + kq;
        rah[i] = *(const uint4*)(Ahi + off);
        ral[i] = *(const uint4*)(Alo + off);
    }
    #pragma unroll
    for (int i = 0; i < 2; i++) {
        int idx = i * 256 + t;
        int kp = idx >> 5, nq = (idx & 31) * 4;
        size_t off = (size_t)kp * N + bcol + nq;
        rbh[i] = *(const uint4*)(Bhi + off);
        rbl[i] = *(const uint4*)(Blo + off);
    }

    for (int s = 0; s < S; s++) {
        // ---- store to smem ----
        #pragma unroll
        for (int i = 0; i < 2; i++) {
            int idx = i * 256 + t;
            int m = idx >> 2, kq = (idx & 3) * 4;
            sAh[kq + 0][m] = rah[i].x;  sAl[kq + 0][m] = ral[i].x;
            sAh[kq + 1][m] = rah[i].y;  sAl[kq + 1][m] = ral[i].y;
            sAh[kq + 2][m] = rah[i].z;  sAl[kq + 2][m] = ral[i].z;
            sAh[kq + 3][m] = rah[i].w;  sAl[kq + 3][m] = ral[i].w;
        }
        #pragma unroll
        for (int i = 0; i < 2; i++) {
            int idx = i * 256 + t;
            int kp = idx >> 5, nq = (idx & 31) * 4;
            *(uint4*)&sBh[kp][nq] = rbh[i];
            *(uint4*)&sBl[kp][nq] = rbl[i];
        }
        __syncthreads();

        // ---- prefetch next stage ----
        if (s + 1 < S) {
            const int kb = (s + 1) * 16;   // uint32 kpair base
            #pragma unroll
            for (int i = 0; i < 2; i++) {
                int idx = i * 256 + t;
                int m = idx >> 2, kq = (idx & 3) * 4;
                size_t off = (size_t)(brow + m) * K2 + kb + kq;
                rah[i] = *(const uint4*)(Ahi + off);
                ral[i] = *(const uint4*)(Alo + off);
            }
            #pragma unroll
            for (int i = 0; i < 2; i++) {
                int idx = i * 256 + t;
                int kp = idx >> 5, nq = (idx & 31) * 4;
                size_t off = (size_t)(kb + kp) * N + bcol + nq;
                rbh[i] = *(const uint4*)(Bhi + off);
                rbl[i] = *(const uint4*)(Blo + off);
            }
        }

        // ---- compute: 2 x k16 steps ----
        #pragma unroll
        for (int ks = 0; ks < 2; ks++) {
            uint32_t bh[4][2], bl[4][2];
            #pragma unroll
            for (int nf = 0; nf < 4; nf++) {
                const int col = wc * 32 + nf * 8 + g;
                bh[nf][0] = sBh[ks * 8 + cq][col];
                bh[nf][1] = sBh[ks * 8 + cq + 4][col];
                bl[nf][0] = sBl[ks * 8 + cq][col];
                bl[nf][1] = sBl[ks * 8 + cq + 4][col];
            }
            #pragma unroll
            for (int mf = 0; mf < 4; mf++) {
                const int row = wr * 64 + mf * 16;
                uint32_t ah[4], al[4];
                ah[0] = sAh[ks * 8 + cq][row + g];
                ah[1] = sAh[ks * 8 + cq][row + g + 8];
                ah[2] = sAh[ks * 8 + cq + 4][row + g];
                ah[3] = sAh[ks * 8 + cq + 4][row + g + 8];
                al[0] = sAl[ks * 8 + cq][row + g];
                al[1] = sAl[ks * 8 + cq][row + g + 8];
                al[2] = sAl[ks * 8 + cq + 4][row + g];
                al[3] = sAl[ks * 8 + cq + 4][row + g + 8];
                #pragma unroll
                for (int nf = 0; nf < 4; nf++) mma16816(c[mf][nf], ah, bh[nf]);
                #pragma unroll
                for (int nf = 0; nf < 4; nf++) mma16816(c[mf][nf], ah, bl[nf]);
                #pragma unroll
                for (int nf = 0; nf < 4; nf++) mma16816(c[mf][nf], al, bh[nf]);
            }
        }
        __syncthreads();
    }

    // ---- epilogue ----
    #pragma unroll
    for (int mf = 0; mf < 4; mf++) {
        const int row = brow + wr * 64 + mf * 16 + g;
        #pragma unroll
        for (int nf = 0; nf < 4; nf++) {
            const int col = bcol + wc * 32 + nf * 8 + cq * 2;
            float2 v0 = make_float2(c[mf][nf][0], c[mf][nf][1]);
            float2 v1 = make_float2(c[mf][nf][2], c[mf][nf][3]);
            if (BIAS) {
                float2 bv = *(const float2*)(bias + col);
                v0.x += bv.x; v0.y += bv.y;
                v1.x += bv.x; v1.y += bv.y;
            }
            if (RELU) {
                v0.x = fmaxf(v0.x, 0.f); v0.y = fmaxf(v0.y, 0.f);
                v1.x = fmaxf(v1.x, 0.f); v1.y = fmaxf(v1.y, 0.f);
            }
            if (OUTBF16) {
                uint32_t h0, l0, h1, l1;
                split2(v0.x, v0.y, h0, l0);
                split2(v1.x, v1.y, h1, l1);
                const size_t p0 = ((size_t)row * N + col) >> 1;
                const size_t p1 = ((size_t)(row + 8) * N + col) >> 1;
                Chi[p0] = h0;  Clo[p0] = l0;
                Chi[p1] = h1;  Clo[p1] = l1;
            } else {
                *(float2*)(C + (size_t)row * N + col)       = v0;
                *(float2*)(C + (size_t)(row + 8) * N + col) = v1;
            }
        }
    }
}

// ======================================================================
// Causal flash attention, fp32, DEPTH=64. 64-query x 64-key tiles.
// Output: ctx as bf16 hi/lo (split fused into epilogue).
// ======================================================================
#define ATTN_SMEM ((64*64*2 + 64*68*2) * 4)

__global__ __launch_bounds__(256)
void attn_kernel(const float* __restrict__ qkv,
                 uint32_t* __restrict__ ctxh, uint32_t* __restrict__ ctxl)
{
    extern __shared__ float sm[];
    float* Qs = sm;               // [d][q]  64x64 (depth-major)
    float* Ks = Qs + 64 * 64;     // [d][k]  64x64
    float* Vs = Ks + 64 * 64;     // [k][d]  pitch 68
    float* Ps = Vs + 64 * 68;     // [k][q]  pitch 68

    const int qt = (gridDim.x - 1) - blockIdx.x;   // heavy tiles first
    const int bh = blockIdx.y;
    const int b  = bh / HH;
    const int h  = bh % HH;

    const float* base = qkv + (size_t)b * SS * (3 * DD);

    const int t  = threadIdx.x;
    const int ty = t >> 4, tx = t & 15;
    const int r0 = ty * 4, c0 = tx * 4;

    const int lr = t & 63;
    const int ld = (t >> 6) * 16;

    {
        const float* qp = base + (size_t)(qt * 64 + lr) * (3 * DD) + h * 64 + ld;
        #pragma unroll
        for (int i = 0; i < 16; i += 4) {
            float4 v4 = *(const float4*)(qp + i);
            Qs[(ld + i + 0) * 64 + lr] = v4.x * 0.125f;
            Qs[(ld + i + 1) * 64 + lr] = v4.y * 0.125f;
            Qs[(ld + i + 2) * 64 + lr] = v4.z * 0.125f;
            Qs[(ld + i + 3) * 64 + lr] = v4.w * 0.125f;
        }
    }

    float O[4][4];
    float m[4], l[4];
    #pragma unroll
    for (int i = 0; i < 4; i++) {
        m[i] = -1e30f; l[i] = 0.f;
        #pragma unroll
        for (int j = 0; j < 4; j++) O[i][j] = 0.f;
    }

    for (int kt = 0; kt <= qt; kt++) {
        __syncthreads();
        {
            const float* kp = base + (size_t)(kt * 64 + lr) * (3 * DD) + DD + h * 64 + ld;
            const float* vp = kp + DD;
            #pragma unroll
            for (int i = 0; i < 16; i += 4) {
                float4 kv = *(const float4*)(kp + i);
                Ks[(ld + i + 0) * 64 + lr] = kv.x;
                Ks[(ld + i + 1) * 64 + lr] = kv.y;
                Ks[(ld + i + 2) * 64 + lr] = kv.z;
                Ks[(ld + i + 3) * 64 + lr] = kv.w;
                float4 vv = *(const float4*)(vp + i);
                *(float4*)&Vs[lr * 68 + ld + i] = vv;
            }
        }
        __syncthreads();

        float s[4][4];
        #pragma unroll
        for (int i = 0; i < 4; i++)
            #pragma unroll
            for (int j = 0; j < 4; j++) s[i][j] = 0.f;

        #pragma unroll 4
        for (int d = 0; d < 64; d++) {
            float4 a  = *(const float4*)&Qs[d * 64 + r0];
            float4 bq = *(const float4*)&Ks[d * 64 + c0];
            float raf[4] = {a.x, a.y, a.z, a.w};
            float rbf[4] = {bq.x, bq.y, bq.z, bq.w};
            #pragma unroll
            for (int i = 0; i < 4; i++)
                #pragma unroll
                for (int j = 0; j < 4; j++)
                    s[i][j] = fmaf(raf[i], rbf[j], s[i][j]);
        }

        if (kt == qt) {
            #pragma unroll
            for (int i = 0; i < 4; i++)
                #pragma unroll
                for (int j = 0; j < 4; j++)
                    if (c0 + j > r0 + i) s[i][j] = -1e30f;
        }

        #pragma unroll
        for (int i = 0; i < 4; i++) {
            float rmax = fmaxf(fmaxf(s[i][0], s[i][1]), fmaxf(s[i][2], s[i][3]));
            #pragma unroll
            for (int o = 8; o >= 1; o >>= 1)
                rmax = fmaxf(rmax, __shfl_xor_sync(0xffffffffu, rmax, o));
            float mn = fmaxf(m[i], rmax);
            float scale = __expf(m[i] - mn);
            float rsum = 0.f;
            #pragma unroll
            for (int j = 0; j < 4; j++) {
                float p = __expf(s[i][j] - mn);
                s[i][j] = p;
                rsum += p;
            }
            #pragma unroll
            for (int o = 8; o >= 1; o >>= 1)
                rsum += __shfl_xor_sync(0xffffffffu, rsum, o);
            l[i] = l[i] * scale + rsum;
            m[i] = mn;
            #pragma unroll
            for (int j = 0; j < 4; j++) O[i][j] *= scale;
        }

        #pragma unroll
        for (int j = 0; j < 4; j++)
            #pragma unroll
            for (int i = 0; i < 4; i++)
                Ps[(c0 + j) * 68 + (r0 + i)] = s[i][j];
        __syncthreads();

        #pragma unroll 4
        for (int k = 0; k < 64; k++) {
            float4 pv = *(const float4*)&Ps[k * 68 + r0];
            float4 vv = *(const float4*)&Vs[k * 68 + c0];
            float rp[4] = {pv.x, pv.y, pv.z, pv.w};
            float rv[4] = {vv.x, vv.y, vv.z, vv.w};
            #pragma unroll
            for (int i = 0; i < 4; i++)
                #pragma unroll
                for (int j = 0; j < 4; j++)
                    O[i][j] = fmaf(rp[i], rv[j], O[i][j]);
        }
    }

    // epilogue: fused bf16 hi/lo split of ctx
    #pragma unroll
    for (int i = 0; i < 4; i++) {
        const float inv = 1.f / l[i];
        const size_t pos = (size_t)(b * SS + qt * 64 + r0 + i) * DD + h * 64 + c0;
        uint32_t h0, l0, h1, l1;
        split2(O[i][0] * inv, O[i][1] * inv, h0, l0);
        split2(O[i][2] * inv, O[i][3] * inv, h1, l1);
        uint2 vh = make_uint2(h0, h1);
        uint2 vl = make_uint2(l0, l1);
        *(uint2*)&ctxh[pos >> 1] = vh;
        *(uint2*)&ctxl[pos >> 1] = vl;
    }
}

// ======================================================================
// Fused residual + LayerNorm (+ optional bf16 hi/lo emit), row length 768.
// ======================================================================
template<bool WB>
__global__ __launch_bounds__(256)
void ln_residual(const float* __restrict__ a, const float* __restrict__ b,
                 const float* __restrict__ gain, const float* __restrict__ beta,
                 float* __restrict__ out,
                 __nv_bfloat16* __restrict__ ohi, __nv_bfloat16* __restrict__ olo)
{
    const int row = blockIdx.x;
    const float* pa = a + (size_t)row * DD;
    const float* pb = b + (size_t)row * DD;

    float v[3];
    float s = 0.f, s2 = 0.f;
    #pragma unroll
    for (int i = 0; i < 3; i++) {
        const int c = threadIdx.x + i * 256;
        float x = pa[c] + pb[c];
        v[i] = x;
        s  += x;
        s2 = fmaf(x, x, s2);
    }

    __shared__ float sm1[8], sm2[8];
    #pragma unroll
    for (int o = 16; o >= 1; o >>= 1) {
        s  += __shfl_xor_sync(0xffffffffu, s,  o);
        s2 += __shfl_xor_sync(0xffffffffu, s2, o);
    }
    const int w = threadIdx.x >> 5, lane = threadIdx.x & 31;
    if (lane == 0) { sm1[w] = s; sm2[w] = s2; }
    __syncthreads();
    if (w == 0) {
        s  = (lane < 8) ? sm1[lane] : 0.f;
        s2 = (lane < 8) ? sm2[lane] : 0.f;
        #pragma unroll
        for (int o = 4; o >= 1; o >>= 1) {
            s  += __shfl_xor_sync(0xffffffffu, s,  o);
            s2 += __shfl_xor_sync(0xffffffffu, s2, o);
        }
        if (lane == 0) { sm1[0] = s; sm2[0] = s2; }
    }
    __syncthreads();

    const float mean = sm1[0] * (1.f / DD);
    const float var  = sm2[0] * (1.f / DD) - mean * mean;
    const float inv  = rsqrtf(var + LN_EPS);

    #pragma unroll
    for (int i = 0; i < 3; i++) {
        const int c = threadIdx.x + i * 256;
        const size_t p = (size_t)row * DD + c;
        float y = gain[c] * (v[i] - mean) * inv + beta[c];
        out[p] = y;
        if (WB) {
            __nv_bfloat16 yh = __float2bfloat16(y);
            ohi[p] = yh;
            olo[p] = __float2bfloat16(y - __bfloat162float(yh));
        }
    }
}

// ======================================================================
// launch
// ======================================================================
extern "C" void kernel_launch(void* const* d_in, const int* in_sizes, int n_in,
                              void* d_out, int out_size)
{
    const float* x    = (const float*)d_in[0];
    const float* Wqkv = (const float*)d_in[1];
    const float* Wout = (const float*)d_in[2];
    const float* bout = (const float*)d_in[3];
    const float* W1   = (const float*)d_in[4];
    const float* b1   = (const float*)d_in[5];
    const float* W2   = (const float*)d_in[6];
    const float* b2   = (const float*)d_in[7];
    const float* g1   = (const float*)d_in[8];
    const float* be1  = (const float*)d_in[9];
    const float* g2   = (const float*)d_in[10];
    const float* be2  = (const float*)d_in[11];
    float* out = (float*)d_out;

    float *qkv, *tmp, *h;
    uint32_t *xh, *xl, *ctxh, *ctxl, *hh, *hl, *ffh, *ffl;
    uint32_t *wqkvh, *wqkvl, *wouth, *woutl, *w1h, *w1l, *w2h, *w2l;
    cudaGetSymbolAddress((void**)&qkv,  g_qkv);
    cudaGetSymbolAddress((void**)&tmp,  g_tmp);
    cudaGetSymbolAddress((void**)&h,    g_h);
    cudaGetSymbolAddress((void**)&xh,   g_xh);
    cudaGetSymbolAddress((void**)&xl,   g_xl);
    cudaGetSymbolAddress((void**)&ctxh, g_ctxh);
    cudaGetSymbolAddress((void**)&ctxl, g_ctxl);
    cudaGetSymbolAddress((void**)&hh,   g_hh);
    cudaGetSymbolAddress((void**)&hl,   g_hl);
    cudaGetSymbolAddress((void**)&ffh,  g_ffh);
    cudaGetSymbolAddress((void**)&ffl,  g_ffl);
    cudaGetSymbolAddress((void**)&wqkvh, g_wqkvh);
    cudaGetSymbolAddress((void**)&wqkvl, g_wqkvl);
    cudaGetSymbolAddress((void**)&wouth, g_wouth);
    cudaGetSymbolAddress((void**)&woutl, g_woutl);
    cudaGetSymbolAddress((void**)&w1h,   g_w1h);
    cudaGetSymbolAddress((void**)&w1l,   g_w1l);
    cudaGetSymbolAddress((void**)&w2h,   g_w2h);
    cudaGetSymbolAddress((void**)&w2l,   g_w2l);

    cudaFuncSetAttribute(attn_kernel,
                         cudaFuncAttributeMaxDynamicSharedMemorySize, ATTN_SMEM);

    dim3 blk(256);

    // ---- operand pre-splits ----
    split_wgt<<<((DD/2)*3*DD + 255)/256, blk>>>(Wqkv, wqkvh, wqkvl, DD/2, 3*DD);
    split_wgt<<<((DD/2)*DD   + 255)/256, blk>>>(Wout, wouth, woutl, DD/2, DD);
    split_wgt<<<((DD/2)*DFF  + 255)/256, blk>>>(W1,   w1h,   w1l,   DD/2, DFF);
    split_wgt<<<((DFF/2)*DD  + 255)/256, blk>>>(W2,   w2h,   w2l,   DFF/2, DD);
    split_act<<<(NROWS*DD/2  + 255)/256, blk>>>(x,    xh,    xl,    NROWS*DD/2);

    // 1) QKV projection: (4096x768) @ (768x2304) -> fp32 qkv
    gemm_pre<false, false, false><<<dim3((3*DD)/128, NROWS/128), blk>>>(
        xh, xl, wqkvh, wqkvl, nullptr, qkv, nullptr, nullptr, NROWS, 3*DD, DD);

    // 2) causal attention -> ctx (bf16 hi/lo)
    attn_kernel<<<dim3(SS/64, BB*HH), blk, ATTN_SMEM>>>(qkv, ctxh, ctxl);

    // 3) output projection + bias -> fp32 tmp
    gemm_pre<true, false, false><<<dim3(DD/128, NROWS/128), blk>>>(
        ctxh, ctxl, wouth, woutl, bout, tmp, nullptr, nullptr, NROWS, DD, DD);

    // 4) LN1(x + attn_out) -> h (fp32 + bf16 hi/lo)
    ln_residual<true><<<NROWS, 256>>>(x, tmp, g1, be1, h,
                                      (__nv_bfloat16*)hh, (__nv_bfloat16*)hl);

    // 5) FFN up + bias + relu -> ff (bf16 hi/lo only)
    gemm_pre<true, true, true><<<dim3(DFF/128, NROWS/128), blk>>>(
        hh, hl, w1h, w1l, b1, nullptr, ffh, ffl, NROWS, DFF, DD);

    // 6) FFN down + bias -> fp32 tmp
    gemm_pre<true, false, false><<<dim3(DD/128, NROWS/128), blk>>>(
        ffh, ffl, w2h, w2l, b2, tmp, nullptr, nullptr, NROWS, DD, DFF);

    // 7) LN2(h + ff) -> out
    ln_residual<false><<<NROWS, 256>>>(h, tmp, g2, be2, out, nullptr, nullptr);
}